// round 3
// baseline (speedup 1.0000x reference)
#include <cuda_runtime.h>
#include <cstdint>

#define NFEAT 256
#define NHID  128
#define MAX_NODES 50000
#define MAX_EDGES 1600000

// Static device scratch (no allocs allowed in kernel_launch)
__device__ float g_support[(size_t)MAX_NODES * NHID];   // 25.6 MB
__device__ int   g_counts[MAX_NODES + 1];
__device__ int   g_row_off[MAX_NODES + 1];
__device__ int   g_fill[MAX_NODES + 1];
__device__ int2  g_edges[MAX_EDGES];                    // {src, bits(weight)} 12.8 MB

// ---------------------------------------------------------------------------
// SGEMM: out[M,128] = x[M,256] @ w[256,128]
// BM=64, BN=128 (full N), BK=16, 256 threads, 8x4 register tile per thread.
// ---------------------------------------------------------------------------
__global__ __launch_bounds__(256) void gemm_kernel(
    const float* __restrict__ x, const float* __restrict__ w,
    float* __restrict__ out, int M)
{
    __shared__ float As[16][64];
    __shared__ float Bs[16][128];

    const int tid = threadIdx.x;
    const int block_row = blockIdx.x * 64;
    const int tx = tid & 31;
    const int ty = tid >> 5;

    float acc[8][4];
#pragma unroll
    for (int i = 0; i < 8; i++)
#pragma unroll
        for (int j = 0; j < 4; j++) acc[i][j] = 0.f;

    for (int k0 = 0; k0 < NFEAT; k0 += 16) {
        {
            int r  = tid >> 2;
            int kk = (tid & 3) * 4;
            int grow = block_row + r;
            float4 v = make_float4(0.f, 0.f, 0.f, 0.f);
            if (grow < M)
                v = *(const float4*)(x + (size_t)grow * NFEAT + k0 + kk);
            As[kk + 0][r] = v.x;
            As[kk + 1][r] = v.y;
            As[kk + 2][r] = v.z;
            As[kk + 3][r] = v.w;
        }
        {
#pragma unroll
            for (int l = 0; l < 2; l++) {
                int idx = tid + l * 256;
                int kk  = idx >> 5;
                int c4  = (idx & 31) * 4;
                float4 v = *(const float4*)(w + (size_t)(k0 + kk) * NHID + c4);
                *(float4*)&Bs[kk][c4] = v;
            }
        }
        __syncthreads();

#pragma unroll
        for (int kk = 0; kk < 16; kk++) {
            float a[8];
            float4 a0 = *(const float4*)&As[kk][ty * 8];
            float4 a1 = *(const float4*)&As[kk][ty * 8 + 4];
            a[0] = a0.x; a[1] = a0.y; a[2] = a0.z; a[3] = a0.w;
            a[4] = a1.x; a[5] = a1.y; a[6] = a1.z; a[7] = a1.w;
            float4 b = *(const float4*)&Bs[kk][tx * 4];
#pragma unroll
            for (int i = 0; i < 8; i++) {
                acc[i][0] += a[i] * b.x;
                acc[i][1] += a[i] * b.y;
                acc[i][2] += a[i] * b.z;
                acc[i][3] += a[i] * b.w;
            }
        }
        __syncthreads();
    }

#pragma unroll
    for (int i = 0; i < 8; i++) {
        int grow = block_row + ty * 8 + i;
        if (grow < M) {
            float4 v = make_float4(acc[i][0], acc[i][1], acc[i][2], acc[i][3]);
            *(float4*)(out + (size_t)grow * NHID + tx * 4) = v;
        }
    }
}

// ---------------------------------------------------------------------------
// CSR build step 1: zero per-node counters
// ---------------------------------------------------------------------------
__global__ void zero_counts_kernel(int* __restrict__ counts, int n)
{
    int i = blockIdx.x * blockDim.x + threadIdx.x;
    if (i < n) counts[i] = 0;
}

// CSR build step 2: histogram of dst
__global__ void hist_kernel(const int* __restrict__ dst, int* __restrict__ counts, int E)
{
    int e = blockIdx.x * blockDim.x + threadIdx.x;
    if (e < E) atomicAdd(&counts[__ldg(dst + e)], 1);
}

// CSR build step 3: exclusive scan (single block, 1024 threads)
__global__ __launch_bounds__(1024) void scan_kernel(
    const int* __restrict__ counts, int* __restrict__ row_off,
    int* __restrict__ fill, int M)
{
    __shared__ int s[1024];
    int t = threadIdx.x;
    int C = (M + 1023) >> 10;
    int b = t * C;

    int sum = 0;
    for (int i = 0; i < C; i++) {
        int idx = b + i;
        if (idx < M) sum += counts[idx];
    }
    s[t] = sum;
    __syncthreads();

    // Hillis-Steele inclusive scan over 1024 partials
    for (int o = 1; o < 1024; o <<= 1) {
        int v = (t >= o) ? s[t - o] : 0;
        __syncthreads();
        s[t] += v;
        __syncthreads();
    }

    int offset = s[t] - sum;   // exclusive prefix for this thread's chunk
    for (int i = 0; i < C; i++) {
        int idx = b + i;
        if (idx < M) {
            row_off[idx] = offset;
            fill[idx]    = offset;
            offset += counts[idx];
        }
    }
    if (t == 1023) row_off[M] = s[1023];
}

// CSR build step 4: reorder edges into dst-grouped order (packed 8B writes)
__global__ void reorder_kernel(
    const int* __restrict__ src, const int* __restrict__ dst,
    const float* __restrict__ ew, int* __restrict__ fill,
    int2* __restrict__ edges, int E)
{
    int e = blockIdx.x * blockDim.x + threadIdx.x;
    if (e < E) {
        int d = __ldg(dst + e);
        int p = atomicAdd(&fill[d], 1);
        edges[p] = make_int2(__ldg(src + e), __float_as_int(__ldg(ew + e)));
    }
}

// ---------------------------------------------------------------------------
// Fused gather + bias + relu + log_softmax. Warp per dst node.
// Lane owns 4 contiguous output features (float4); accumulate in registers.
// 2-edge ILP in the inner loop to cover L2 latency.
// ---------------------------------------------------------------------------
__global__ __launch_bounds__(256) void gather_finalize_kernel(
    const float* __restrict__ support,
    const int2*  __restrict__ edges,
    const int*   __restrict__ row_off,
    const float* __restrict__ bias,
    float*       __restrict__ out,
    int M)
{
    int node = (blockIdx.x * blockDim.x + threadIdx.x) >> 5;
    int lane = threadIdx.x & 31;
    if (node >= M) return;

    int e0 = row_off[node];
    int e1 = row_off[node + 1];

    float4 acc0 = make_float4(0.f, 0.f, 0.f, 0.f);
    float4 acc1 = make_float4(0.f, 0.f, 0.f, 0.f);

    for (int base = e0; base < e1; base += 32) {
        int n = e1 - base; if (n > 32) n = 32;
        int2 ed = make_int2(0, 0);
        if (lane < n) ed = edges[base + lane];

        int i = 0;
        for (; i + 2 <= n; i += 2) {
            int   s0 = __shfl_sync(0xffffffffu, ed.x, i);
            float w0 = __int_as_float(__shfl_sync(0xffffffffu, ed.y, i));
            int   s1 = __shfl_sync(0xffffffffu, ed.x, i + 1);
            float w1 = __int_as_float(__shfl_sync(0xffffffffu, ed.y, i + 1));
            float4 v0 = *(const float4*)(support + (size_t)s0 * NHID + lane * 4);
            float4 v1 = *(const float4*)(support + (size_t)s1 * NHID + lane * 4);
            acc0.x += w0 * v0.x; acc0.y += w0 * v0.y;
            acc0.z += w0 * v0.z; acc0.w += w0 * v0.w;
            acc1.x += w1 * v1.x; acc1.y += w1 * v1.y;
            acc1.z += w1 * v1.z; acc1.w += w1 * v1.w;
        }
        if (i < n) {
            int   s = __shfl_sync(0xffffffffu, ed.x, i);
            float w = __int_as_float(__shfl_sync(0xffffffffu, ed.y, i));
            float4 v = *(const float4*)(support + (size_t)s * NHID + lane * 4);
            acc0.x += w * v.x; acc0.y += w * v.y;
            acc0.z += w * v.z; acc0.w += w * v.w;
        }
    }

    // Epilogue: bias + relu
    float4 b = *(const float4*)(bias + lane * 4);
    float4 h;
    h.x = fmaxf(acc0.x + acc1.x + b.x, 0.f);
    h.y = fmaxf(acc0.y + acc1.y + b.y, 0.f);
    h.z = fmaxf(acc0.z + acc1.z + b.z, 0.f);
    h.w = fmaxf(acc0.w + acc1.w + b.w, 0.f);

    // log_softmax over the 128 features (warp reduce)
    float m = fmaxf(fmaxf(h.x, h.y), fmaxf(h.z, h.w));
#pragma unroll
    for (int o = 16; o > 0; o >>= 1)
        m = fmaxf(m, __shfl_xor_sync(0xffffffffu, m, o));

    float ssum = expf(h.x - m) + expf(h.y - m) + expf(h.z - m) + expf(h.w - m);
#pragma unroll
    for (int o = 16; o > 0; o >>= 1)
        ssum += __shfl_xor_sync(0xffffffffu, ssum, o);

    float lse = m + logf(ssum);
    h.x -= lse; h.y -= lse; h.z -= lse; h.w -= lse;
    *(float4*)(out + (size_t)node * NHID + lane * 4) = h;
}

// ---------------------------------------------------------------------------
// Launch. Inputs: x[f32 M*256], weight[f32 256*128], bias[f32 128],
// edge_index[i32 2*E], edge_weight[f32 E]. Output f32 M*128.
// ---------------------------------------------------------------------------
extern "C" void kernel_launch(void* const* d_in, const int* in_sizes, int n_in,
                              void* d_out, int out_size)
{
    const float* x    = (const float*)d_in[0];
    const float* w    = (const float*)d_in[1];
    const float* bias = (const float*)d_in[2];
    const int*   ei   = (const int*)d_in[3];
    const float* ew   = (const float*)d_in[4];
    float* out = (float*)d_out;

    const int M = in_sizes[0] / NFEAT;      // 50000
    const int E = in_sizes[4];              // 1,600,000
    const int* src = ei;
    const int* dst = ei + E;

    float* support; cudaGetSymbolAddress((void**)&support, g_support);
    int*   counts;  cudaGetSymbolAddress((void**)&counts,  g_counts);
    int*   row_off; cudaGetSymbolAddress((void**)&row_off, g_row_off);
    int*   fill;    cudaGetSymbolAddress((void**)&fill,    g_fill);
    int2*  edges;   cudaGetSymbolAddress((void**)&edges,   g_edges);

    // 1) support = x @ W
    gemm_kernel<<<(M + 63) / 64, 256>>>(x, w, support, M);

    // 2) CSR build by dst
    zero_counts_kernel<<<(M + 255) / 256, 256>>>(counts, M);
    hist_kernel<<<(E + 255) / 256, 256>>>(dst, counts, E);
    scan_kernel<<<1, 1024>>>(counts, row_off, fill, M);
    reorder_kernel<<<(E + 255) / 256, 256>>>(src, dst, ew, fill, edges, E);

    // 3) fused gather + bias + relu + log_softmax
    gather_finalize_kernel<<<(M + 7) / 8, 256>>>(support, edges, row_off, bias, out, M);
}

// round 4
// speedup vs baseline: 1.3471x; 1.3471x over previous
#include <cuda_runtime.h>
#include <cstdint>

#define NFEAT 256
#define NHID  128
#define MAX_NODES 50000
#define MAX_EDGES 1600000
#define SCAN_CHUNK 512

// Static device scratch (no allocs allowed in kernel_launch)
__device__ float g_support[(size_t)MAX_NODES * NHID];   // 25.6 MB
__device__ int   g_counts[MAX_NODES + 1];
__device__ int   g_row_off[MAX_NODES + 1];
__device__ int   g_fill[MAX_NODES + 1];
__device__ int   g_partials[(MAX_NODES + SCAN_CHUNK - 1) / SCAN_CHUNK + 1];
__device__ int2  g_edges[MAX_EDGES];                    // {src, bits(weight)} 12.8 MB

// ---------------------------------------------------------------------------
// SGEMM: out[M,128] = x[M,256] @ w[256,128]
// BM=64, BN=128 (full N), BK=16, 256 threads, 8x4 register tile per thread.
// ---------------------------------------------------------------------------
__global__ __launch_bounds__(256) void gemm_kernel(
    const float* __restrict__ x, const float* __restrict__ w,
    float* __restrict__ out, int M)
{
    __shared__ float As[16][64];
    __shared__ float Bs[16][128];

    const int tid = threadIdx.x;
    const int block_row = blockIdx.x * 64;
    const int tx = tid & 31;
    const int ty = tid >> 5;

    float acc[8][4];
#pragma unroll
    for (int i = 0; i < 8; i++)
#pragma unroll
        for (int j = 0; j < 4; j++) acc[i][j] = 0.f;

    for (int k0 = 0; k0 < NFEAT; k0 += 16) {
        {
            int r  = tid >> 2;
            int kk = (tid & 3) * 4;
            int grow = block_row + r;
            float4 v = make_float4(0.f, 0.f, 0.f, 0.f);
            if (grow < M)
                v = *(const float4*)(x + (size_t)grow * NFEAT + k0 + kk);
            As[kk + 0][r] = v.x;
            As[kk + 1][r] = v.y;
            As[kk + 2][r] = v.z;
            As[kk + 3][r] = v.w;
        }
        {
#pragma unroll
            for (int l = 0; l < 2; l++) {
                int idx = tid + l * 256;
                int kk  = idx >> 5;
                int c4  = (idx & 31) * 4;
                float4 v = *(const float4*)(w + (size_t)(k0 + kk) * NHID + c4);
                *(float4*)&Bs[kk][c4] = v;
            }
        }
        __syncthreads();

#pragma unroll
        for (int kk = 0; kk < 16; kk++) {
            float a[8];
            float4 a0 = *(const float4*)&As[kk][ty * 8];
            float4 a1 = *(const float4*)&As[kk][ty * 8 + 4];
            a[0] = a0.x; a[1] = a0.y; a[2] = a0.z; a[3] = a0.w;
            a[4] = a1.x; a[5] = a1.y; a[6] = a1.z; a[7] = a1.w;
            float4 b = *(const float4*)&Bs[kk][tx * 4];
#pragma unroll
            for (int i = 0; i < 8; i++) {
                acc[i][0] += a[i] * b.x;
                acc[i][1] += a[i] * b.y;
                acc[i][2] += a[i] * b.z;
                acc[i][3] += a[i] * b.w;
            }
        }
        __syncthreads();
    }

#pragma unroll
    for (int i = 0; i < 8; i++) {
        int grow = block_row + ty * 8 + i;
        if (grow < M) {
            float4 v = make_float4(acc[i][0], acc[i][1], acc[i][2], acc[i][3]);
            *(float4*)(out + (size_t)grow * NHID + tx * 4) = v;
        }
    }
}

// ---------------------------------------------------------------------------
// CSR build step 1: zero per-node counters
// ---------------------------------------------------------------------------
__global__ void zero_counts_kernel(int* __restrict__ counts, int n)
{
    int i = blockIdx.x * blockDim.x + threadIdx.x;
    if (i < n) counts[i] = 0;
}

// CSR build step 2: histogram of dst
__global__ void hist_kernel(const int* __restrict__ dst, int* __restrict__ counts, int E)
{
    int e = blockIdx.x * blockDim.x + threadIdx.x;
    if (e < E) atomicAdd(&counts[__ldg(dst + e)], 1);
}

// ---------------------------------------------------------------------------
// CSR build step 3: multi-block exclusive scan (3 phases, all parallel)
// ---------------------------------------------------------------------------
// 3a: per-block reduce of SCAN_CHUNK counters -> partials[block]
__global__ __launch_bounds__(SCAN_CHUNK) void scan_partials_kernel(
    const int* __restrict__ counts, int* __restrict__ partials, int M)
{
    __shared__ int s[SCAN_CHUNK];
    int t = threadIdx.x;
    int idx = blockIdx.x * SCAN_CHUNK + t;
    s[t] = (idx < M) ? counts[idx] : 0;
    __syncthreads();
#pragma unroll
    for (int o = SCAN_CHUNK / 2; o > 0; o >>= 1) {
        if (t < o) s[t] += s[t + o];
        __syncthreads();
    }
    if (t == 0) partials[blockIdx.x] = s[0];
}

// 3b: single small block exclusive-scans the partials (NB <= 128)
__global__ __launch_bounds__(128) void scan_tops_kernel(
    int* __restrict__ partials, int* __restrict__ row_off, int NB, int M)
{
    __shared__ int s[128];
    int t = threadIdx.x;
    int v = (t < NB) ? partials[t] : 0;
    s[t] = v;
    __syncthreads();
#pragma unroll
    for (int o = 1; o < 128; o <<= 1) {
        int u = (t >= o) ? s[t - o] : 0;
        __syncthreads();
        s[t] += u;
        __syncthreads();
    }
    if (t < NB) partials[t] = s[t] - v;   // exclusive prefix per block
    if (t == 127) row_off[M] = s[127];    // total edge count
}

// 3c: per-block exclusive scan of its chunk + block prefix -> row_off, fill
__global__ __launch_bounds__(SCAN_CHUNK) void scan_final_kernel(
    const int* __restrict__ counts, const int* __restrict__ partials,
    int* __restrict__ row_off, int* __restrict__ fill, int M)
{
    __shared__ int s[SCAN_CHUNK];
    int t = threadIdx.x;
    int idx = blockIdx.x * SCAN_CHUNK + t;
    int v = (idx < M) ? counts[idx] : 0;
    s[t] = v;
    __syncthreads();
#pragma unroll
    for (int o = 1; o < SCAN_CHUNK; o <<= 1) {
        int u = (t >= o) ? s[t - o] : 0;
        __syncthreads();
        s[t] += u;
        __syncthreads();
    }
    int excl = s[t] - v + partials[blockIdx.x];
    if (idx < M) {
        row_off[idx] = excl;
        fill[idx]    = excl;
    }
}

// CSR build step 4: reorder edges into dst-grouped order (packed 8B writes)
__global__ void reorder_kernel(
    const int* __restrict__ src, const int* __restrict__ dst,
    const float* __restrict__ ew, int* __restrict__ fill,
    int2* __restrict__ edges, int E)
{
    int e = blockIdx.x * blockDim.x + threadIdx.x;
    if (e < E) {
        int d = __ldg(dst + e);
        int p = atomicAdd(&fill[d], 1);
        edges[p] = make_int2(__ldg(src + e), __float_as_int(__ldg(ew + e)));
    }
}

// ---------------------------------------------------------------------------
// Fused gather + bias + relu + log_softmax. Warp per dst node.
// Lane owns 4 contiguous output features (float4); accumulate in registers.
// 2-edge ILP in the inner loop to cover L2 latency.
// ---------------------------------------------------------------------------
__global__ __launch_bounds__(256) void gather_finalize_kernel(
    const float* __restrict__ support,
    const int2*  __restrict__ edges,
    const int*   __restrict__ row_off,
    const float* __restrict__ bias,
    float*       __restrict__ out,
    int M)
{
    int node = (blockIdx.x * blockDim.x + threadIdx.x) >> 5;
    int lane = threadIdx.x & 31;
    if (node >= M) return;

    int e0 = row_off[node];
    int e1 = row_off[node + 1];

    float4 acc0 = make_float4(0.f, 0.f, 0.f, 0.f);
    float4 acc1 = make_float4(0.f, 0.f, 0.f, 0.f);

    for (int base = e0; base < e1; base += 32) {
        int n = e1 - base; if (n > 32) n = 32;
        int2 ed = make_int2(0, 0);
        if (lane < n) ed = edges[base + lane];

        int i = 0;
        for (; i + 2 <= n; i += 2) {
            int   s0 = __shfl_sync(0xffffffffu, ed.x, i);
            float w0 = __int_as_float(__shfl_sync(0xffffffffu, ed.y, i));
            int   s1 = __shfl_sync(0xffffffffu, ed.x, i + 1);
            float w1 = __int_as_float(__shfl_sync(0xffffffffu, ed.y, i + 1));
            float4 v0 = *(const float4*)(support + (size_t)s0 * NHID + lane * 4);
            float4 v1 = *(const float4*)(support + (size_t)s1 * NHID + lane * 4);
            acc0.x += w0 * v0.x; acc0.y += w0 * v0.y;
            acc0.z += w0 * v0.z; acc0.w += w0 * v0.w;
            acc1.x += w1 * v1.x; acc1.y += w1 * v1.y;
            acc1.z += w1 * v1.z; acc1.w += w1 * v1.w;
        }
        if (i < n) {
            int   s = __shfl_sync(0xffffffffu, ed.x, i);
            float w = __int_as_float(__shfl_sync(0xffffffffu, ed.y, i));
            float4 v = *(const float4*)(support + (size_t)s * NHID + lane * 4);
            acc0.x += w * v.x; acc0.y += w * v.y;
            acc0.z += w * v.z; acc0.w += w * v.w;
        }
    }

    // Epilogue: bias + relu
    float4 b = *(const float4*)(bias + lane * 4);
    float4 h;
    h.x = fmaxf(acc0.x + acc1.x + b.x, 0.f);
    h.y = fmaxf(acc0.y + acc1.y + b.y, 0.f);
    h.z = fmaxf(acc0.z + acc1.z + b.z, 0.f);
    h.w = fmaxf(acc0.w + acc1.w + b.w, 0.f);

    // log_softmax over the 128 features (warp reduce)
    float m = fmaxf(fmaxf(h.x, h.y), fmaxf(h.z, h.w));
#pragma unroll
    for (int o = 16; o > 0; o >>= 1)
        m = fmaxf(m, __shfl_xor_sync(0xffffffffu, m, o));

    float ssum = expf(h.x - m) + expf(h.y - m) + expf(h.z - m) + expf(h.w - m);
#pragma unroll
    for (int o = 16; o > 0; o >>= 1)
        ssum += __shfl_xor_sync(0xffffffffu, ssum, o);

    float lse = m + logf(ssum);
    h.x -= lse; h.y -= lse; h.z -= lse; h.w -= lse;
    *(float4*)(out + (size_t)node * NHID + lane * 4) = h;
}

// ---------------------------------------------------------------------------
// Launch. Inputs: x[f32 M*256], weight[f32 256*128], bias[f32 128],
// edge_index[i32 2*E], edge_weight[f32 E]. Output f32 M*128.
// ---------------------------------------------------------------------------
extern "C" void kernel_launch(void* const* d_in, const int* in_sizes, int n_in,
                              void* d_out, int out_size)
{
    const float* x    = (const float*)d_in[0];
    const float* w    = (const float*)d_in[1];
    const float* bias = (const float*)d_in[2];
    const int*   ei   = (const int*)d_in[3];
    const float* ew   = (const float*)d_in[4];
    float* out = (float*)d_out;

    const int M = in_sizes[0] / NFEAT;      // 50000
    const int E = in_sizes[4];              // 1,600,000
    const int* src = ei;
    const int* dst = ei + E;

    float* support;  cudaGetSymbolAddress((void**)&support,  g_support);
    int*   counts;   cudaGetSymbolAddress((void**)&counts,   g_counts);
    int*   row_off;  cudaGetSymbolAddress((void**)&row_off,  g_row_off);
    int*   fill;     cudaGetSymbolAddress((void**)&fill,     g_fill);
    int*   partials; cudaGetSymbolAddress((void**)&partials, g_partials);
    int2*  edges;    cudaGetSymbolAddress((void**)&edges,    g_edges);

    const int NB = (M + SCAN_CHUNK - 1) / SCAN_CHUNK;   // 98 for M=50000

    // 1) support = x @ W
    gemm_kernel<<<(M + 63) / 64, 256>>>(x, w, support, M);

    // 2) CSR build by dst (parallel scan)
    zero_counts_kernel<<<(M + 255) / 256, 256>>>(counts, M);
    hist_kernel<<<(E + 255) / 256, 256>>>(dst, counts, E);
    scan_partials_kernel<<<NB, SCAN_CHUNK>>>(counts, partials, M);
    scan_tops_kernel<<<1, 128>>>(partials, row_off, NB, M);
    scan_final_kernel<<<NB, SCAN_CHUNK>>>(counts, partials, row_off, fill, M);
    reorder_kernel<<<(E + 255) / 256, 256>>>(src, dst, ew, fill, edges, E);

    // 3) fused gather + bias + relu + log_softmax
    gather_finalize_kernel<<<(M + 7) / 8, 256>>>(support, edges, row_off, bias, out, M);
}

// round 5
// speedup vs baseline: 1.3745x; 1.0203x over previous
#include <cuda_runtime.h>
#include <cuda_fp16.h>
#include <cstdint>

#define NFEAT 256
#define NHID  128
#define MAX_NODES 50000
#define MAX_EDGES 1600000
#define SCAN_CHUNK 512

// Static device scratch (no allocs allowed in kernel_launch)
__device__ __half g_support[(size_t)MAX_NODES * NHID];  // 12.8 MB (fp16)
__device__ int    g_counts[MAX_NODES + 1];
__device__ int    g_row_off[MAX_NODES + 1];
__device__ int    g_fill[MAX_NODES + 1];
__device__ int    g_partials[(MAX_NODES + SCAN_CHUNK - 1) / SCAN_CHUNK + 1];
__device__ int2   g_edges[MAX_EDGES];                   // {src, bits(weight)} 12.8 MB

// ---------------------------------------------------------------------------
// SGEMM: support[M,128] = x[M,256] @ w[256,128], fp32 accum, fp16 store.
// BM=64, BN=128 (full N), BK=16, 256 threads, 8x4 register tile per thread.
// ---------------------------------------------------------------------------
__global__ __launch_bounds__(256) void gemm_kernel(
    const float* __restrict__ x, const float* __restrict__ w,
    __half* __restrict__ out, int M)
{
    __shared__ float As[16][64];
    __shared__ float Bs[16][128];

    const int tid = threadIdx.x;
    const int block_row = blockIdx.x * 64;
    const int tx = tid & 31;
    const int ty = tid >> 5;

    float acc[8][4];
#pragma unroll
    for (int i = 0; i < 8; i++)
#pragma unroll
        for (int j = 0; j < 4; j++) acc[i][j] = 0.f;

    for (int k0 = 0; k0 < NFEAT; k0 += 16) {
        {
            int r  = tid >> 2;
            int kk = (tid & 3) * 4;
            int grow = block_row + r;
            float4 v = make_float4(0.f, 0.f, 0.f, 0.f);
            if (grow < M)
                v = *(const float4*)(x + (size_t)grow * NFEAT + k0 + kk);
            As[kk + 0][r] = v.x;
            As[kk + 1][r] = v.y;
            As[kk + 2][r] = v.z;
            As[kk + 3][r] = v.w;
        }
        {
#pragma unroll
            for (int l = 0; l < 2; l++) {
                int idx = tid + l * 256;
                int kk  = idx >> 5;
                int c4  = (idx & 31) * 4;
                float4 v = *(const float4*)(w + (size_t)(k0 + kk) * NHID + c4);
                *(float4*)&Bs[kk][c4] = v;
            }
        }
        __syncthreads();

#pragma unroll
        for (int kk = 0; kk < 16; kk++) {
            float a[8];
            float4 a0 = *(const float4*)&As[kk][ty * 8];
            float4 a1 = *(const float4*)&As[kk][ty * 8 + 4];
            a[0] = a0.x; a[1] = a0.y; a[2] = a0.z; a[3] = a0.w;
            a[4] = a1.x; a[5] = a1.y; a[6] = a1.z; a[7] = a1.w;
            float4 b = *(const float4*)&Bs[kk][tx * 4];
#pragma unroll
            for (int i = 0; i < 8; i++) {
                acc[i][0] += a[i] * b.x;
                acc[i][1] += a[i] * b.y;
                acc[i][2] += a[i] * b.z;
                acc[i][3] += a[i] * b.w;
            }
        }
        __syncthreads();
    }

#pragma unroll
    for (int i = 0; i < 8; i++) {
        int grow = block_row + ty * 8 + i;
        if (grow < M) {
            __half2 p0 = __floats2half2_rn(acc[i][0], acc[i][1]);
            __half2 p1 = __floats2half2_rn(acc[i][2], acc[i][3]);
            int2 packed;
            packed.x = *(int*)&p0;
            packed.y = *(int*)&p1;
            *(int2*)(out + (size_t)grow * NHID + tx * 4) = packed;
        }
    }
}

// ---------------------------------------------------------------------------
// CSR build step 1: zero per-node counters
// ---------------------------------------------------------------------------
__global__ void zero_counts_kernel(int* __restrict__ counts, int n)
{
    int i = blockIdx.x * blockDim.x + threadIdx.x;
    if (i < n) counts[i] = 0;
}

// CSR build step 2: histogram of dst
__global__ void hist_kernel(const int* __restrict__ dst, int* __restrict__ counts, int E)
{
    int e = blockIdx.x * blockDim.x + threadIdx.x;
    if (e < E) atomicAdd(&counts[__ldg(dst + e)], 1);
}

// ---------------------------------------------------------------------------
// CSR build step 3: multi-block exclusive scan (3 phases, all parallel)
// ---------------------------------------------------------------------------
__global__ __launch_bounds__(SCAN_CHUNK) void scan_partials_kernel(
    const int* __restrict__ counts, int* __restrict__ partials, int M)
{
    __shared__ int s[SCAN_CHUNK];
    int t = threadIdx.x;
    int idx = blockIdx.x * SCAN_CHUNK + t;
    s[t] = (idx < M) ? counts[idx] : 0;
    __syncthreads();
#pragma unroll
    for (int o = SCAN_CHUNK / 2; o > 0; o >>= 1) {
        if (t < o) s[t] += s[t + o];
        __syncthreads();
    }
    if (t == 0) partials[blockIdx.x] = s[0];
}

__global__ __launch_bounds__(128) void scan_tops_kernel(
    int* __restrict__ partials, int* __restrict__ row_off, int NB, int M)
{
    __shared__ int s[128];
    int t = threadIdx.x;
    int v = (t < NB) ? partials[t] : 0;
    s[t] = v;
    __syncthreads();
#pragma unroll
    for (int o = 1; o < 128; o <<= 1) {
        int u = (t >= o) ? s[t - o] : 0;
        __syncthreads();
        s[t] += u;
        __syncthreads();
    }
    if (t < NB) partials[t] = s[t] - v;   // exclusive prefix per block
    if (t == 127) row_off[M] = s[127];    // total edge count
}

__global__ __launch_bounds__(SCAN_CHUNK) void scan_final_kernel(
    const int* __restrict__ counts, const int* __restrict__ partials,
    int* __restrict__ row_off, int* __restrict__ fill, int M)
{
    __shared__ int s[SCAN_CHUNK];
    int t = threadIdx.x;
    int idx = blockIdx.x * SCAN_CHUNK + t;
    int v = (idx < M) ? counts[idx] : 0;
    s[t] = v;
    __syncthreads();
#pragma unroll
    for (int o = 1; o < SCAN_CHUNK; o <<= 1) {
        int u = (t >= o) ? s[t - o] : 0;
        __syncthreads();
        s[t] += u;
        __syncthreads();
    }
    int excl = s[t] - v + partials[blockIdx.x];
    if (idx < M) {
        row_off[idx] = excl;
        fill[idx]    = excl;
    }
}

// CSR build step 4: reorder edges into dst-grouped order (packed 8B writes)
__global__ void reorder_kernel(
    const int* __restrict__ src, const int* __restrict__ dst,
    const float* __restrict__ ew, int* __restrict__ fill,
    int2* __restrict__ edges, int E)
{
    int e = blockIdx.x * blockDim.x + threadIdx.x;
    if (e < E) {
        int d = __ldg(dst + e);
        int p = atomicAdd(&fill[d], 1);
        edges[p] = make_int2(__ldg(src + e), __float_as_int(__ldg(ew + e)));
    }
}

// ---------------------------------------------------------------------------
// Fused gather + bias + relu + log_softmax. Warp per dst node.
// Lane owns 4 contiguous features; fp16 support rows (8 B/lane/edge loads),
// fp32 accumulation, 4-edge ILP to cover L2 latency.
// ---------------------------------------------------------------------------
__device__ __forceinline__ void fma_edge(float4& acc, float w, int2 raw)
{
    __half2 h0 = *(__half2*)&raw.x;
    __half2 h1 = *(__half2*)&raw.y;
    float2 f0 = __half22float2(h0);
    float2 f1 = __half22float2(h1);
    acc.x += w * f0.x; acc.y += w * f0.y;
    acc.z += w * f1.x; acc.w += w * f1.y;
}

__global__ __launch_bounds__(256) void gather_finalize_kernel(
    const __half* __restrict__ support,
    const int2*   __restrict__ edges,
    const int*    __restrict__ row_off,
    const float*  __restrict__ bias,
    float*        __restrict__ out,
    int M)
{
    int node = (blockIdx.x * blockDim.x + threadIdx.x) >> 5;
    int lane = threadIdx.x & 31;
    if (node >= M) return;

    int e0 = row_off[node];
    int e1 = row_off[node + 1];

    float4 acc0 = make_float4(0.f, 0.f, 0.f, 0.f);
    float4 acc1 = make_float4(0.f, 0.f, 0.f, 0.f);
    float4 acc2 = make_float4(0.f, 0.f, 0.f, 0.f);
    float4 acc3 = make_float4(0.f, 0.f, 0.f, 0.f);

    for (int base = e0; base < e1; base += 32) {
        int n = e1 - base; if (n > 32) n = 32;
        int2 ed = make_int2(0, 0);
        if (lane < n) ed = edges[base + lane];

        int i = 0;
        for (; i + 4 <= n; i += 4) {
            int   s0 = __shfl_sync(0xffffffffu, ed.x, i);
            float w0 = __int_as_float(__shfl_sync(0xffffffffu, ed.y, i));
            int   s1 = __shfl_sync(0xffffffffu, ed.x, i + 1);
            float w1 = __int_as_float(__shfl_sync(0xffffffffu, ed.y, i + 1));
            int   s2 = __shfl_sync(0xffffffffu, ed.x, i + 2);
            float w2 = __int_as_float(__shfl_sync(0xffffffffu, ed.y, i + 2));
            int   s3 = __shfl_sync(0xffffffffu, ed.x, i + 3);
            float w3 = __int_as_float(__shfl_sync(0xffffffffu, ed.y, i + 3));
            int2 r0 = *(const int2*)(support + (size_t)s0 * NHID + lane * 4);
            int2 r1 = *(const int2*)(support + (size_t)s1 * NHID + lane * 4);
            int2 r2 = *(const int2*)(support + (size_t)s2 * NHID + lane * 4);
            int2 r3 = *(const int2*)(support + (size_t)s3 * NHID + lane * 4);
            fma_edge(acc0, w0, r0);
            fma_edge(acc1, w1, r1);
            fma_edge(acc2, w2, r2);
            fma_edge(acc3, w3, r3);
        }
        for (; i < n; i++) {
            int   s = __shfl_sync(0xffffffffu, ed.x, i);
            float w = __int_as_float(__shfl_sync(0xffffffffu, ed.y, i));
            int2 r = *(const int2*)(support + (size_t)s * NHID + lane * 4);
            fma_edge(acc0, w, r);
        }
    }

    // Epilogue: bias + relu
    float4 b = *(const float4*)(bias + lane * 4);
    float4 h;
    h.x = fmaxf(acc0.x + acc1.x + acc2.x + acc3.x + b.x, 0.f);
    h.y = fmaxf(acc0.y + acc1.y + acc2.y + acc3.y + b.y, 0.f);
    h.z = fmaxf(acc0.z + acc1.z + acc2.z + acc3.z + b.z, 0.f);
    h.w = fmaxf(acc0.w + acc1.w + acc2.w + acc3.w + b.w, 0.f);

    // log_softmax over the 128 features (warp reduce)
    float m = fmaxf(fmaxf(h.x, h.y), fmaxf(h.z, h.w));
#pragma unroll
    for (int o = 16; o > 0; o >>= 1)
        m = fmaxf(m, __shfl_xor_sync(0xffffffffu, m, o));

    float ssum = expf(h.x - m) + expf(h.y - m) + expf(h.z - m) + expf(h.w - m);
#pragma unroll
    for (int o = 16; o > 0; o >>= 1)
        ssum += __shfl_xor_sync(0xffffffffu, ssum, o);

    float lse = m + logf(ssum);
    h.x -= lse; h.y -= lse; h.z -= lse; h.w -= lse;
    *(float4*)(out + (size_t)node * NHID + lane * 4) = h;
}

// ---------------------------------------------------------------------------
// Launch. Inputs: x[f32 M*256], weight[f32 256*128], bias[f32 128],
// edge_index[i32 2*E], edge_weight[f32 E]. Output f32 M*128.
// ---------------------------------------------------------------------------
extern "C" void kernel_launch(void* const* d_in, const int* in_sizes, int n_in,
                              void* d_out, int out_size)
{
    const float* x    = (const float*)d_in[0];
    const float* w    = (const float*)d_in[1];
    const float* bias = (const float*)d_in[2];
    const int*   ei   = (const int*)d_in[3];
    const float* ew   = (const float*)d_in[4];
    float* out = (float*)d_out;

    const int M = in_sizes[0] / NFEAT;      // 50000
    const int E = in_sizes[4];              // 1,600,000
    const int* src = ei;
    const int* dst = ei + E;

    __half* support; cudaGetSymbolAddress((void**)&support,  g_support);
    int*   counts;   cudaGetSymbolAddress((void**)&counts,   g_counts);
    int*   row_off;  cudaGetSymbolAddress((void**)&row_off,  g_row_off);
    int*   fill;     cudaGetSymbolAddress((void**)&fill,     g_fill);
    int*   partials; cudaGetSymbolAddress((void**)&partials, g_partials);
    int2*  edges;    cudaGetSymbolAddress((void**)&edges,    g_edges);

    const int NB = (M + SCAN_CHUNK - 1) / SCAN_CHUNK;   // 98 for M=50000

    // 1) support = x @ W (fp32 accum, fp16 store)
    gemm_kernel<<<(M + 63) / 64, 256>>>(x, w, support, M);

    // 2) CSR build by dst (parallel scan)
    zero_counts_kernel<<<(M + 255) / 256, 256>>>(counts, M);
    hist_kernel<<<(E + 255) / 256, 256>>>(dst, counts, E);
    scan_partials_kernel<<<NB, SCAN_CHUNK>>>(counts, partials, M);
    scan_tops_kernel<<<1, 128>>>(partials, row_off, NB, M);
    scan_final_kernel<<<NB, SCAN_CHUNK>>>(counts, partials, row_off, fill, M);
    reorder_kernel<<<(E + 255) / 256, 256>>>(src, dst, ew, fill, edges, E);

    // 3) fused gather + bias + relu + log_softmax
    gather_finalize_kernel<<<(M + 7) / 8, 256>>>(support, edges, row_off, bias, out, M);
}